// round 3
// baseline (speedup 1.0000x reference)
#include <cuda_runtime.h>
#include <cstddef>

#define NN   100000
#define EE   1600000
#define GG   100
#define NPG  1000
#define HH   128
#define FIN  64
#define RD   64
#define SLOPE 0.01f
#define EPSN  1e-5f

// ---------------- scratch (device globals; no allocation allowed) ----------------
__device__ int   d_cnt_in[NN];
__device__ int   d_cnt_out[NN];
__device__ int   d_cursor[NN];
__device__ int   d_rowstart[NN + 1];
__device__ int   d_srcs[EE];
__device__ float d_ws[EE];
__device__ float d_outis[NN];
__device__ float d_inis[NN];
__device__ float d_hpre[(size_t)NN * HH];
__device__ float d_conv[(size_t)NN * HH];
__device__ float d_hpost[(size_t)NN * HH];
__device__ float d_phi[(size_t)NN * HH];
__device__ float d_pool1[GG * HH];
__device__ float d_m1[GG * HH];
__device__ float d_pool2[GG * HH];
__device__ float d_m2[GG * HH];

__device__ __forceinline__ float leaky(float x) { return x >= 0.f ? x : SLOPE * x; }

// ---------------- init / degree / CSR build ----------------
__global__ __launch_bounds__(256) void zero_kernel() {
    int i = blockIdx.x * blockDim.x + threadIdx.x;
    if (i < NN) { d_cnt_in[i] = 0; d_cnt_out[i] = 0; d_cursor[i] = 0; }
}

__global__ __launch_bounds__(256)
void hist_kernel(const int* __restrict__ src, const int* __restrict__ dst) {
    int e = blockIdx.x * blockDim.x + threadIdx.x;
    if (e < EE) {
        atomicAdd(&d_cnt_out[src[e]], 1);
        atomicAdd(&d_cnt_in[dst[e]], 1);
    }
}

__global__ __launch_bounds__(256) void isqrt_kernel() {
    int i = blockIdx.x * blockDim.x + threadIdx.x;
    if (i < NN) {
        int co = d_cnt_out[i]; if (co < 1) co = 1;
        int ci = d_cnt_in[i];  if (ci < 1) ci = 1;
        d_outis[i] = rsqrtf((float)co);
        d_inis[i]  = rsqrtf((float)ci);
    }
}

// single-CTA exclusive scan of cnt_in -> rowstart (256 threads, bounded regs)
__global__ __launch_bounds__(256) void scan_kernel() {
    __shared__ int sm[256];
    const int CH = 391;  // 391*256 = 100096 >= NN
    int t = threadIdx.x;
    int base = t * CH;
    int s = 0;
    for (int i = 0; i < CH; i++) {
        int idx = base + i;
        if (idx < NN) s += d_cnt_in[idx];
    }
    sm[t] = s;
    __syncthreads();
    for (int off = 1; off < 256; off <<= 1) {
        int v = 0;
        if (t >= off) v = sm[t - off];
        __syncthreads();
        sm[t] += v;
        __syncthreads();
    }
    int run = (t == 0) ? 0 : sm[t - 1];
    for (int i = 0; i < CH; i++) {
        int idx = base + i;
        if (idx < NN) {
            d_rowstart[idx] = run;
            run += d_cnt_in[idx];
        }
    }
    if (t == 255) d_rowstart[NN] = sm[255];
}

__global__ __launch_bounds__(256)
void fill_kernel(const int* __restrict__ src, const int* __restrict__ dst,
                 const float* __restrict__ ew) {
    int e = blockIdx.x * blockDim.x + threadIdx.x;
    if (e < EE) {
        int d = dst[e];
        int p = d_rowstart[d] + atomicAdd(&d_cursor[d], 1);
        d_srcs[p] = src[e];
        d_ws[p]   = ew[e];
    }
}

// ---------------- dense GEMM: Y[r, 0:128] (+)= scale(r) * X[r, koff:koff+64] @ W(64x128) ----------------
template <bool ACC, bool BL>
__global__ __launch_bounds__(256)
void gemm_k64(const float* __restrict__ X, int ldx, int koff,
              const float* __restrict__ W,          // 64 x 128 row-major
              const float* __restrict__ rowscale,   // may be null
              const float* __restrict__ bias,       // used when BL
              float* __restrict__ Y) {
    __shared__ float Wsm[64 * 128];
    int tid = threadIdx.x;
    for (int i = tid; i < 64 * 128; i += 256) Wsm[i] = W[i];
    __syncthreads();

    int r = blockIdx.x * 256 + tid;
    if (r >= NN) return;

    float xv[64];
    const float4* xp = (const float4*)(X + (size_t)r * ldx + koff);
#pragma unroll
    for (int i = 0; i < 16; i++) {
        float4 v = xp[i];
        xv[4 * i + 0] = v.x; xv[4 * i + 1] = v.y;
        xv[4 * i + 2] = v.z; xv[4 * i + 3] = v.w;
    }
    if (rowscale) {
        float s = rowscale[r];
#pragma unroll
        for (int i = 0; i < 64; i++) xv[i] *= s;
    }

    float* yp = Y + (size_t)r * 128;
    for (int jc = 0; jc < 16; jc++) {
        float acc[8];
#pragma unroll
        for (int j = 0; j < 8; j++) acc[j] = 0.f;
#pragma unroll
        for (int k = 0; k < 64; k++) {
            const float4* w4 = (const float4*)(Wsm + k * 128 + jc * 8);
            float4 wa = w4[0], wb = w4[1];
            float x = xv[k];
            acc[0] += x * wa.x; acc[1] += x * wa.y;
            acc[2] += x * wa.z; acc[3] += x * wa.w;
            acc[4] += x * wb.x; acc[5] += x * wb.y;
            acc[6] += x * wb.z; acc[7] += x * wb.w;
        }
        float4 o0 = make_float4(acc[0], acc[1], acc[2], acc[3]);
        float4 o1 = make_float4(acc[4], acc[5], acc[6], acc[7]);
        if (ACC) {
            float4 p0 = ((const float4*)yp)[jc * 2 + 0];
            float4 p1 = ((const float4*)yp)[jc * 2 + 1];
            o0.x += p0.x; o0.y += p0.y; o0.z += p0.z; o0.w += p0.w;
            o1.x += p1.x; o1.y += p1.y; o1.z += p1.z; o1.w += p1.w;
        }
        if (BL) {
            const float* b = bias + jc * 8;
            o0.x = leaky(o0.x + b[0]); o0.y = leaky(o0.y + b[1]);
            o0.z = leaky(o0.z + b[2]); o0.w = leaky(o0.w + b[3]);
            o1.x = leaky(o1.x + b[4]); o1.y = leaky(o1.y + b[5]);
            o1.z = leaky(o1.z + b[6]); o1.w = leaky(o1.w + b[7]);
        }
        ((float4*)yp)[jc * 2 + 0] = o0;
        ((float4*)yp)[jc * 2 + 1] = o1;
    }
}

// ---------------- edge aggregation (CSR by dst, warp per node) ----------------
__global__ __launch_bounds__(256)
void conv_kernel(const float* __restrict__ hpre, float* __restrict__ out) {
    int gt = blockIdx.x * blockDim.x + threadIdx.x;
    int node = gt >> 5;
    int lane = gt & 31;
    if (node >= NN) return;
    int e0 = d_rowstart[node];
    int e1 = d_rowstart[node + 1];
    const float4* hp = (const float4*)hpre;
    float4 acc = make_float4(0.f, 0.f, 0.f, 0.f);
    for (int e = e0; e < e1; e++) {
        int s = d_srcs[e];
        float w = d_ws[e];
        float4 v = hp[(size_t)s * 32 + lane];
        acc.x += v.x * w; acc.y += v.y * w;
        acc.z += v.z * w; acc.w += v.w * w;
    }
    float sc = d_inis[node];
    acc.x *= sc; acc.y *= sc; acc.z *= sc; acc.w *= sc;
    ((float4*)out)[(size_t)node * 32 + lane] = acc;
}

// ---------------- GraphNorm + leaky (CTA per graph) ----------------
__global__ __launch_bounds__(256)
void norm_kernel(const float* __restrict__ Yin,
                 const float* __restrict__ alpha, const float* __restrict__ gamma_,
                 const float* __restrict__ beta, float* __restrict__ Yout) {
    int g = blockIdx.x;
    int f = threadIdx.x & 127;
    int half = threadIdx.x >> 7;  // 0 or 1, each handles 500 nodes
    const float* base = Yin + ((size_t)g * NPG + half * 500) * HH + f;
    float s1 = 0.f, s2 = 0.f;
#pragma unroll 4
    for (int i = 0; i < 500; i++) {
        float v = base[(size_t)i * HH];
        s1 += v;
        s2 += v * v;
    }
    __shared__ float sm1[256], sm2[256];
    sm1[threadIdx.x] = s1;
    sm2[threadIdx.x] = s2;
    __syncthreads();
    float S1 = sm1[f] + sm1[128 + f];
    float S2 = sm2[f] + sm2[128 + f];
    float a = alpha[f], gm = gamma_[f], bt = beta[f];
    float mean = S1 * (1.f / NPG);
    float var = S2 * (1.f / NPG) - (2.f * a - a * a) * mean * mean;
    float inv = rsqrtf(var + EPSN);
    float am = a * mean;
    float* obase = Yout + ((size_t)g * NPG + half * 500) * HH + f;
#pragma unroll 4
    for (int i = 0; i < 500; i++) {
        float v = base[(size_t)i * HH];
        float o = gm * (v - am) * inv + bt;
        obase[(size_t)i * HH] = leaky(o);
    }
}

// ---------------- per-graph mean pool ----------------
__global__ __launch_bounds__(128)
void pool_kernel(const float* __restrict__ X, float* __restrict__ out) {
    int g = blockIdx.x;
    int f = threadIdx.x;
    const float* base = X + (size_t)g * NPG * HH + f;
    float s0 = 0.f, s1 = 0.f, s2 = 0.f, s3 = 0.f;
    for (int i = 0; i < NPG; i += 4) {
        s0 += base[(size_t)(i + 0) * HH];
        s1 += base[(size_t)(i + 1) * HH];
        s2 += base[(size_t)(i + 2) * HH];
        s3 += base[(size_t)(i + 3) * HH];
    }
    out[g * HH + f] = (s0 + s1 + s2 + s3) * (1.f / NPG);
}

// ---------------- final readout assembly ----------------
__global__ __launch_bounds__(128)
void final_kernel(const float* __restrict__ p1, const float* __restrict__ m1,
                  const float* __restrict__ p2, const float* __restrict__ m2,
                  const float* __restrict__ r1w2, const float* __restrict__ r1b2,
                  const float* __restrict__ r2w2, const float* __restrict__ r2b2,
                  float* __restrict__ out) {
    int g = blockIdx.x;
    int t = threadIdx.x;
    if (t < RD) {
        float a1 = r1b2[t], a2 = r2b2[t];
        const float* pp1 = p1 + g * HH;
        const float* pp2 = p2 + g * HH;
#pragma unroll 4
        for (int f = 0; f < HH; f++) {
            a1 += pp1[f] * r1w2[f * RD + t];
            a2 += pp2[f] * r2w2[f * RD + t];
        }
        out[g * 384 + t]       = leaky(leaky(a1));
        out[g * 384 + 192 + t] = leaky(leaky(a2));
    }
    out[g * 384 + 64 + t]  = leaky(m1[g * HH + t]);
    out[g * 384 + 256 + t] = leaky(m2[g * HH + t]);
}

// ---------------- host launch ----------------
extern "C" void kernel_launch(void* const* d_in, const int* in_sizes, int n_in,
                              void* d_out, int out_size) {
    const float* node_feats = (const float*)d_in[0];
    const float* ew         = (const float*)d_in[1];
    const float* W1         = (const float*)d_in[2];
    const float* W2         = (const float*)d_in[3];
    const float* gn1a       = (const float*)d_in[4];
    const float* gn1g       = (const float*)d_in[5];
    const float* gn1b       = (const float*)d_in[6];
    const float* gn2a       = (const float*)d_in[7];
    const float* gn2g       = (const float*)d_in[8];
    const float* gn2b       = (const float*)d_in[9];
    const float* r1w1       = (const float*)d_in[10];
    const float* r1b1       = (const float*)d_in[11];
    const float* r1w2       = (const float*)d_in[12];
    const float* r1b2       = (const float*)d_in[13];
    const float* r2w1       = (const float*)d_in[14];
    const float* r2b1       = (const float*)d_in[15];
    const float* r2w2       = (const float*)d_in[16];
    const float* r2b2       = (const float*)d_in[17];
    const int*   src        = (const int*)d_in[18];
    const int*   dst        = (const int*)d_in[19];
    float* out = (float*)d_out;

    void *hpre, *conv, *hpost, *phi, *pool1, *m1, *pool2, *m2, *outis;
    cudaGetSymbolAddress(&hpre,  d_hpre);
    cudaGetSymbolAddress(&conv,  d_conv);
    cudaGetSymbolAddress(&hpost, d_hpost);
    cudaGetSymbolAddress(&phi,   d_phi);
    cudaGetSymbolAddress(&pool1, d_pool1);
    cudaGetSymbolAddress(&m1,    d_m1);
    cudaGetSymbolAddress(&pool2, d_pool2);
    cudaGetSymbolAddress(&m2,    d_m2);
    cudaGetSymbolAddress(&outis, d_outis);

    const int NB = (NN + 255) / 256;       // 391
    const int EB = (EE + 255) / 256;       // 6250
    const int CB = (NN * 32 + 255) / 256;  // 12500

    // CSR build + degrees
    zero_kernel<<<NB, 256>>>();
    hist_kernel<<<EB, 256>>>(src, dst);
    isqrt_kernel<<<NB, 256>>>();
    scan_kernel<<<1, 256>>>();
    fill_kernel<<<EB, 256>>>(src, dst, ew);

    // ---- layer 1 ----
    gemm_k64<false, false><<<NB, 256>>>(node_feats, FIN, 0, W1, (const float*)outis, nullptr, (float*)hpre);
    conv_kernel<<<CB, 256>>>((const float*)hpre, (float*)conv);
    norm_kernel<<<GG, 256>>>((const float*)conv, gn1a, gn1g, gn1b, (float*)hpost);

    // readout1 phi + pools
    gemm_k64<false, false><<<NB, 256>>>((const float*)hpost, HH, 0,  r1w1,            nullptr, nullptr, (float*)phi);
    gemm_k64<true,  true ><<<NB, 256>>>((const float*)hpost, HH, 64, r1w1 + 64 * HH,  nullptr, r1b1,    (float*)phi);
    pool_kernel<<<GG, 128>>>((const float*)phi,   (float*)pool1);
    pool_kernel<<<GG, 128>>>((const float*)hpost, (float*)m1);

    // ---- layer 2 ----
    gemm_k64<false, false><<<NB, 256>>>((const float*)hpost, HH, 0,  W2,            (const float*)outis, nullptr, (float*)hpre);
    gemm_k64<true,  false><<<NB, 256>>>((const float*)hpost, HH, 64, W2 + 64 * HH,  (const float*)outis, nullptr, (float*)hpre);
    conv_kernel<<<CB, 256>>>((const float*)hpre, (float*)conv);
    norm_kernel<<<GG, 256>>>((const float*)conv, gn2a, gn2g, gn2b, (float*)hpost);

    gemm_k64<false, false><<<NB, 256>>>((const float*)hpost, HH, 0,  r2w1,            nullptr, nullptr, (float*)phi);
    gemm_k64<true,  true ><<<NB, 256>>>((const float*)hpost, HH, 64, r2w1 + 64 * HH,  nullptr, r2b1,    (float*)phi);
    pool_kernel<<<GG, 128>>>((const float*)phi,   (float*)pool2);
    pool_kernel<<<GG, 128>>>((const float*)hpost, (float*)m2);

    final_kernel<<<GG, 128>>>((const float*)pool1, (const float*)m1,
                              (const float*)pool2, (const float*)m2,
                              r1w2, r1b2, r2w2, r2b2, out);
}

// round 4
// speedup vs baseline: 1.3705x; 1.3705x over previous
#include <cuda_runtime.h>
#include <cstddef>

#define NN   100000
#define EE   1600000
#define GG   100
#define NPG  1000
#define HH   128
#define FIN  64
#define RD   64
#define SLOPE 0.01f
#define EPSN  1e-5f
#define NBLK 391   // ceil(NN/256)

typedef unsigned long long u64;

__device__ __forceinline__ u64 pack2(float a, float b) {
    u64 r; asm("mov.b64 %0,{%1,%2};" : "=l"(r) : "f"(a), "f"(b)); return r;
}
__device__ __forceinline__ u64 ffma2(u64 a, u64 b, u64 c) {
    u64 d; asm("fma.rn.f32x2 %0,%1,%2,%3;" : "=l"(d) : "l"(a), "l"(b), "l"(c)); return d;
}
__device__ __forceinline__ float2 unpack2(u64 v) {
    float2 f; asm("mov.b64 {%0,%1},%2;" : "=f"(f.x), "=f"(f.y) : "l"(v)); return f;
}
__device__ __forceinline__ float leaky(float x) { return x >= 0.f ? x : SLOPE * x; }

// ---------------- scratch ----------------
__device__ int   d_cnt_in[NN];
__device__ int   d_cnt_out[NN];
__device__ int   d_cursor[NN];
__device__ int   d_rowstart[NN + 1];
__device__ int   d_bsum[512];
__device__ int   d_srcs[EE];
__device__ float d_ws[EE];
__device__ float d_outis[NN];
__device__ float d_inis[NN];
__device__ float d_hpre[(size_t)NN * HH];
__device__ float d_conv[(size_t)NN * HH];
__device__ float d_hpost[(size_t)NN * HH];
__device__ float d_pool1[GG * HH];
__device__ float d_m1[GG * HH];
__device__ float d_pool2[GG * HH];
__device__ float d_m2[GG * HH];

// ---------------- init / degrees ----------------
__global__ __launch_bounds__(256) void zero_kernel() {
    int i = blockIdx.x * blockDim.x + threadIdx.x;
    if (i < NN) { d_cnt_in[i] = 0; d_cnt_out[i] = 0; d_cursor[i] = 0; }
    if (i < GG * HH) { d_pool1[i] = 0.f; d_pool2[i] = 0.f; }
}

__global__ __launch_bounds__(256)
void hist_kernel(const int* __restrict__ src, const int* __restrict__ dst) {
    int e = blockIdx.x * blockDim.x + threadIdx.x;
    if (e < EE) {
        atomicAdd(&d_cnt_out[src[e]], 1);
        atomicAdd(&d_cnt_in[dst[e]], 1);
    }
}

__global__ __launch_bounds__(256) void isqrt_kernel() {
    int i = blockIdx.x * blockDim.x + threadIdx.x;
    if (i < NN) {
        int co = d_cnt_out[i]; if (co < 1) co = 1;
        int ci = d_cnt_in[i];  if (ci < 1) ci = 1;
        d_outis[i] = rsqrtf((float)co);
        d_inis[i]  = rsqrtf((float)ci);
    }
}

// ---------------- parallel scan (3 kernels) ----------------
__global__ __launch_bounds__(256) void scanA_kernel() {
    __shared__ int sm[256];
    int b = blockIdx.x, t = threadIdx.x, i = b * 256 + t;
    sm[t] = (i < NN) ? d_cnt_in[i] : 0;
    __syncthreads();
    for (int o = 128; o > 0; o >>= 1) {
        if (t < o) sm[t] += sm[t + o];
        __syncthreads();
    }
    if (t == 0) d_bsum[b] = sm[0];
}

__global__ __launch_bounds__(512) void scanB_kernel() {
    __shared__ int sm[512];
    int t = threadIdx.x;
    sm[t] = (t < NBLK) ? d_bsum[t] : 0;
    __syncthreads();
    for (int o = 1; o < 512; o <<= 1) {
        int v = 0;
        if (t >= o) v = sm[t - o];
        __syncthreads();
        sm[t] += v;
        __syncthreads();
    }
    if (t < NBLK) d_bsum[t] = (t == 0) ? 0 : sm[t - 1];
}

__global__ __launch_bounds__(256) void scanC_kernel() {
    __shared__ int sm[256];
    int b = blockIdx.x, t = threadIdx.x, i = b * 256 + t;
    int c = (i < NN) ? d_cnt_in[i] : 0;
    sm[t] = c;
    __syncthreads();
    for (int o = 1; o < 256; o <<= 1) {
        int v = 0;
        if (t >= o) v = sm[t - o];
        __syncthreads();
        sm[t] += v;
        __syncthreads();
    }
    if (i < NN) d_rowstart[i] = sm[t] - c + d_bsum[b];
    if (i == 0) d_rowstart[NN] = EE;
}

__global__ __launch_bounds__(256)
void fill_kernel(const int* __restrict__ src, const int* __restrict__ dst,
                 const float* __restrict__ ew) {
    int e = blockIdx.x * blockDim.x + threadIdx.x;
    if (e < EE) {
        int d = dst[e];
        int p = d_rowstart[d] + atomicAdd(&d_cursor[d], 1);
        d_srcs[p] = src[e];
        d_ws[p]   = ew[e];
    }
}

// ---------------- GEMM: row-per-thread, f32x2-packed FFMA, W in dyn smem ----------------
// PM=false: Y[r] = (RS ? scale[r] : 1) * X[r] @ W, 256 rows/CTA
// PM=true : per-graph pool += leaky(X[r]@W + bias), 250 rows/CTA (graph-aligned), no Y
template <int K, bool RS, bool PM>
__global__ __launch_bounds__(256)
void gemm_kernel(const float* __restrict__ X,
                 const float* __restrict__ W,          // K x 128 row-major
                 const float* __restrict__ rowscale,
                 const float* __restrict__ bias,
                 float* __restrict__ Y,
                 float* __restrict__ pool) {
    extern __shared__ float smf[];
    float* Wsm  = smf;                 // K*128
    float* psum = smf + K * 128;       // 128 (PM only)
    float* bsm  = psum + 128;          // 128 (PM only)
    int tid = threadIdx.x;
    for (int i = tid; i < K * 128; i += 256) Wsm[i] = W[i];
    if (PM && tid < 128) { psum[tid] = 0.f; bsm[tid] = bias[tid]; }
    __syncthreads();

    const int RPC = PM ? 250 : 256;
    int r = blockIdx.x * RPC + tid;
    bool active = PM ? (tid < 250) : (r < NN);

    float xv[K];
    if (active) {
        const float4* xp = (const float4*)(X + (size_t)r * K);
#pragma unroll
        for (int i = 0; i < K / 4; i++) {
            float4 v = xp[i];
            xv[4 * i] = v.x; xv[4 * i + 1] = v.y;
            xv[4 * i + 2] = v.z; xv[4 * i + 3] = v.w;
        }
        if (RS) {
            float s = rowscale[r];
#pragma unroll
            for (int i = 0; i < K; i++) xv[i] *= s;
        }
    } else {
#pragma unroll
        for (int i = 0; i < K; i++) xv[i] = 0.f;
    }

    int lane = tid & 31;
    float* yp = (!PM && active) ? (Y + (size_t)r * 128) : nullptr;

    for (int jc = 0; jc < 8; jc++) {   // 8 chunks of 16 cols
        u64 acc[8];
#pragma unroll
        for (int j = 0; j < 8; j++) acc[j] = 0ull;
#pragma unroll 8
        for (int k = 0; k < K; k++) {
            u64 x2 = pack2(xv[k], xv[k]);
            const double2* w = (const double2*)(Wsm + k * 128 + jc * 16);
            double2 w0 = w[0], w1 = w[1], w2 = w[2], w3 = w[3];
            acc[0] = ffma2(x2, __double_as_longlong(w0.x), acc[0]);
            acc[1] = ffma2(x2, __double_as_longlong(w0.y), acc[1]);
            acc[2] = ffma2(x2, __double_as_longlong(w1.x), acc[2]);
            acc[3] = ffma2(x2, __double_as_longlong(w1.y), acc[3]);
            acc[4] = ffma2(x2, __double_as_longlong(w2.x), acc[4]);
            acc[5] = ffma2(x2, __double_as_longlong(w2.y), acc[5]);
            acc[6] = ffma2(x2, __double_as_longlong(w3.x), acc[6]);
            acc[7] = ffma2(x2, __double_as_longlong(w3.y), acc[7]);
        }
        if (!PM) {
            if (yp) {
#pragma unroll
                for (int j = 0; j < 4; j++) {
                    float2 a = unpack2(acc[2 * j]);
                    float2 b = unpack2(acc[2 * j + 1]);
                    ((float4*)yp)[jc * 4 + j] = make_float4(a.x, a.y, b.x, b.y);
                }
            }
        } else {
            float keep = 0.f;
#pragma unroll
            for (int j = 0; j < 16; j++) {
                float2 p = unpack2(acc[j >> 1]);
                float f = (j & 1) ? p.y : p.x;
                float v = active ? leaky(f + bsm[jc * 16 + j]) : 0.f;
                v += __shfl_xor_sync(0xFFFFFFFFu, v, 16);
                v += __shfl_xor_sync(0xFFFFFFFFu, v, 8);
                v += __shfl_xor_sync(0xFFFFFFFFu, v, 4);
                v += __shfl_xor_sync(0xFFFFFFFFu, v, 2);
                v += __shfl_xor_sync(0xFFFFFFFFu, v, 1);
                if (lane == j) keep = v;
            }
            if (lane < 16) atomicAdd(&psum[jc * 16 + lane], keep);
        }
    }
    if (PM) {
        __syncthreads();
        if (tid < 128) atomicAdd(&pool[(blockIdx.x >> 2) * 128 + tid], psum[tid]);
    }
}

// ---------------- edge aggregation (CSR by dst, warp per node) ----------------
__global__ __launch_bounds__(256)
void conv_kernel(const float* __restrict__ hpre, float* __restrict__ out) {
    int gt = blockIdx.x * blockDim.x + threadIdx.x;
    int node = gt >> 5;
    int lane = gt & 31;
    if (node >= NN) return;
    int e0 = d_rowstart[node];
    int e1 = d_rowstart[node + 1];
    const float4* hp = (const float4*)hpre;
    float4 acc = make_float4(0.f, 0.f, 0.f, 0.f);
    for (int e = e0; e < e1; e++) {
        int s = d_srcs[e];
        float w = d_ws[e];
        float4 v = hp[(size_t)s * 32 + lane];
        acc.x += v.x * w; acc.y += v.y * w;
        acc.z += v.z * w; acc.w += v.w * w;
    }
    float sc = d_inis[node];
    acc.x *= sc; acc.y *= sc; acc.z *= sc; acc.w *= sc;
    ((float4*)out)[(size_t)node * 32 + lane] = acc;
}

// ---------------- GraphNorm + leaky + fused mean pool (CTA per graph) ----------------
__global__ __launch_bounds__(256)
void norm_kernel(const float* __restrict__ Yin,
                 const float* __restrict__ alpha, const float* __restrict__ gamma_,
                 const float* __restrict__ beta, float* __restrict__ Yout,
                 float* __restrict__ mout) {
    int g = blockIdx.x;
    int f = threadIdx.x & 127;
    int half = threadIdx.x >> 7;
    const float* base = Yin + ((size_t)g * NPG + half * 500) * HH + f;
    float s1 = 0.f, s2 = 0.f;
#pragma unroll 4
    for (int i = 0; i < 500; i++) {
        float v = base[(size_t)i * HH];
        s1 += v;
        s2 += v * v;
    }
    __shared__ float sm1[256], sm2[256];
    sm1[threadIdx.x] = s1;
    sm2[threadIdx.x] = s2;
    __syncthreads();
    float S1 = sm1[f] + sm1[128 + f];
    float S2 = sm2[f] + sm2[128 + f];
    float a = alpha[f], gm = gamma_[f], bt = beta[f];
    float mean = S1 * (1.f / NPG);
    float var = S2 * (1.f / NPG) - (2.f * a - a * a) * mean * mean;
    float inv = rsqrtf(var + EPSN);
    float am = a * mean;
    float* obase = Yout + ((size_t)g * NPG + half * 500) * HH + f;
    float so = 0.f;
#pragma unroll 4
    for (int i = 0; i < 500; i++) {
        float v = base[(size_t)i * HH];
        float o = leaky(gm * (v - am) * inv + bt);
        obase[(size_t)i * HH] = o;
        so += o;
    }
    __syncthreads();
    sm1[threadIdx.x] = so;
    __syncthreads();
    if (half == 0) mout[g * HH + f] = (sm1[f] + sm1[128 + f]) * (1.f / NPG);
}

// ---------------- final readout assembly ----------------
__global__ __launch_bounds__(128)
void final_kernel(const float* __restrict__ p1, const float* __restrict__ m1,
                  const float* __restrict__ p2, const float* __restrict__ m2,
                  const float* __restrict__ r1w2, const float* __restrict__ r1b2,
                  const float* __restrict__ r2w2, const float* __restrict__ r2b2,
                  float* __restrict__ out) {
    int g = blockIdx.x;
    int t = threadIdx.x;
    const float inv = 1.f / NPG;
    if (t < RD) {
        float a1 = 0.f, a2 = 0.f;
        const float* pp1 = p1 + g * HH;
        const float* pp2 = p2 + g * HH;
#pragma unroll 4
        for (int f = 0; f < HH; f++) {
            a1 += pp1[f] * r1w2[f * RD + t];
            a2 += pp2[f] * r2w2[f * RD + t];
        }
        a1 = a1 * inv + r1b2[t];
        a2 = a2 * inv + r2b2[t];
        out[g * 384 + t]       = leaky(leaky(a1));
        out[g * 384 + 192 + t] = leaky(leaky(a2));
    }
    out[g * 384 + 64 + t]  = leaky(m1[g * HH + t]);
    out[g * 384 + 256 + t] = leaky(m2[g * HH + t]);
}

// ---------------- host launch ----------------
extern "C" void kernel_launch(void* const* d_in, const int* in_sizes, int n_in,
                              void* d_out, int out_size) {
    const float* node_feats = (const float*)d_in[0];
    const float* ew         = (const float*)d_in[1];
    const float* W1         = (const float*)d_in[2];
    const float* W2         = (const float*)d_in[3];
    const float* gn1a       = (const float*)d_in[4];
    const float* gn1g       = (const float*)d_in[5];
    const float* gn1b       = (const float*)d_in[6];
    const float* gn2a       = (const float*)d_in[7];
    const float* gn2g       = (const float*)d_in[8];
    const float* gn2b       = (const float*)d_in[9];
    const float* r1w1       = (const float*)d_in[10];
    const float* r1b1       = (const float*)d_in[11];
    const float* r1w2       = (const float*)d_in[12];
    const float* r1b2       = (const float*)d_in[13];
    const float* r2w1       = (const float*)d_in[14];
    const float* r2b1       = (const float*)d_in[15];
    const float* r2w2       = (const float*)d_in[16];
    const float* r2b2       = (const float*)d_in[17];
    const int*   src        = (const int*)d_in[18];
    const int*   dst        = (const int*)d_in[19];
    float* out = (float*)d_out;

    void *hpre, *conv, *hpost, *pool1, *m1, *pool2, *m2, *outis;
    cudaGetSymbolAddress(&hpre,  d_hpre);
    cudaGetSymbolAddress(&conv,  d_conv);
    cudaGetSymbolAddress(&hpost, d_hpost);
    cudaGetSymbolAddress(&pool1, d_pool1);
    cudaGetSymbolAddress(&m1,    d_m1);
    cudaGetSymbolAddress(&pool2, d_pool2);
    cudaGetSymbolAddress(&m2,    d_m2);
    cudaGetSymbolAddress(&outis, d_outis);

    const int EB = (EE + 255) / 256;       // 6250
    const int CB = (NN * 32 + 255) / 256;  // 12500

    const int SM64  = 64 * 128 * 4 + 256 * 4;
    const int SM128 = 128 * 128 * 4 + 256 * 4;
    cudaFuncSetAttribute((const void*)gemm_kernel<128, true,  false>,
                         cudaFuncAttributeMaxDynamicSharedMemorySize, SM128);
    cudaFuncSetAttribute((const void*)gemm_kernel<128, false, true>,
                         cudaFuncAttributeMaxDynamicSharedMemorySize, SM128);

    // CSR build + degrees
    zero_kernel<<<NBLK, 256>>>();
    hist_kernel<<<EB, 256>>>(src, dst);
    isqrt_kernel<<<NBLK, 256>>>();
    scanA_kernel<<<NBLK, 256>>>();
    scanB_kernel<<<1, 512>>>();
    scanC_kernel<<<NBLK, 256>>>();
    fill_kernel<<<EB, 256>>>(src, dst, ew);

    // ---- layer 1 ----
    gemm_kernel<64, true, false><<<NBLK, 256, SM64>>>(
        node_feats, W1, (const float*)outis, nullptr, (float*)hpre, nullptr);
    conv_kernel<<<CB, 256>>>((const float*)hpre, (float*)conv);
    norm_kernel<<<GG, 256>>>((const float*)conv, gn1a, gn1g, gn1b,
                             (float*)hpost, (float*)m1);

    // readout1 phi (fused pool, no materialized phi)
    gemm_kernel<128, false, true><<<400, 256, SM128>>>(
        (const float*)hpost, r1w1, nullptr, r1b1, nullptr, (float*)pool1);

    // ---- layer 2 ----
    gemm_kernel<128, true, false><<<NBLK, 256, SM128>>>(
        (const float*)hpost, W2, (const float*)outis, nullptr, (float*)hpre, nullptr);
    conv_kernel<<<CB, 256>>>((const float*)hpre, (float*)conv);
    norm_kernel<<<GG, 256>>>((const float*)conv, gn2a, gn2g, gn2b,
                             (float*)hpost, (float*)m2);

    gemm_kernel<128, false, true><<<400, 256, SM128>>>(
        (const float*)hpost, r2w1, nullptr, r2b1, nullptr, (float*)pool2);

    final_kernel<<<GG, 128>>>((const float*)pool1, (const float*)m1,
                              (const float*)pool2, (const float*)m2,
                              r1w2, r1b2, r2w2, r2b2, out);
}

// round 6
// speedup vs baseline: 2.2780x; 1.6622x over previous
#include <cuda_runtime.h>
#include <cstddef>

#define NN   100000
#define EE   1600000
#define GG   100
#define NPG  1000
#define HH   128
#define FIN  64
#define RD   64
#define SLOPE 0.01f
#define EPSN  1e-5f
#define NBLK 391   // ceil(NN/256)

typedef unsigned long long u64;

__device__ __forceinline__ u64 pack2(float a, float b) {
    u64 r; asm("mov.b64 %0,{%1,%2};" : "=l"(r) : "f"(a), "f"(b)); return r;
}
__device__ __forceinline__ u64 ffma2(u64 a, u64 b, u64 c) {
    u64 d; asm("fma.rn.f32x2 %0,%1,%2,%3;" : "=l"(d) : "l"(a), "l"(b), "l"(c)); return d;
}
__device__ __forceinline__ float2 unpack2(u64 v) {
    float2 f; asm("mov.b64 {%0,%1},%2;" : "=f"(f.x), "=f"(f.y) : "l"(v)); return f;
}
__device__ __forceinline__ float leaky(float x) { return x >= 0.f ? x : SLOPE * x; }

// ---------------- scratch ----------------
__device__ int   d_cnt_in[NN];
__device__ int   d_cnt_out[NN];
__device__ int   d_cursor[NN];
__device__ int   d_rowstart[NN + 1];
__device__ int   d_bsum[512];
__device__ int   d_srcs[EE];
__device__ float d_ws[EE];
__device__ float d_outis[NN];
__device__ float d_inis[NN];
__device__ float d_hpre[(size_t)NN * HH];
__device__ float d_conv[(size_t)NN * HH];
__device__ float d_hpost[(size_t)NN * HH];
__device__ float d_pool1[GG * HH];
__device__ float d_m1[GG * HH];
__device__ float d_pool2[GG * HH];
__device__ float d_m2[GG * HH];
__device__ float d_S1a[GG * HH];
__device__ float d_S2a[GG * HH];
__device__ float d_S1b[GG * HH];
__device__ float d_S2b[GG * HH];

// ---------------- init / degrees ----------------
__global__ __launch_bounds__(256) void zero_kernel() {
    int i = blockIdx.x * blockDim.x + threadIdx.x;
    if (i < NN) { d_cnt_in[i] = 0; d_cnt_out[i] = 0; d_cursor[i] = 0; }
    if (i < GG * HH) {
        d_pool1[i] = 0.f; d_pool2[i] = 0.f;
        d_m1[i] = 0.f;    d_m2[i] = 0.f;
        d_S1a[i] = 0.f;   d_S2a[i] = 0.f;
        d_S1b[i] = 0.f;   d_S2b[i] = 0.f;
    }
}

__global__ __launch_bounds__(256)
void hist_kernel(const int* __restrict__ src, const int* __restrict__ dst) {
    int e = blockIdx.x * blockDim.x + threadIdx.x;
    if (e < EE) {
        atomicAdd(&d_cnt_out[src[e]], 1);
        atomicAdd(&d_cnt_in[dst[e]], 1);
    }
}

__global__ __launch_bounds__(256) void isqrt_kernel() {
    int i = blockIdx.x * blockDim.x + threadIdx.x;
    if (i < NN) {
        int co = d_cnt_out[i]; if (co < 1) co = 1;
        int ci = d_cnt_in[i];  if (ci < 1) ci = 1;
        d_outis[i] = rsqrtf((float)co);
        d_inis[i]  = rsqrtf((float)ci);
    }
}

// ---------------- parallel scan (3 kernels) ----------------
__global__ __launch_bounds__(256) void scanA_kernel() {
    __shared__ int sm[256];
    int b = blockIdx.x, t = threadIdx.x, i = b * 256 + t;
    sm[t] = (i < NN) ? d_cnt_in[i] : 0;
    __syncthreads();
    for (int o = 128; o > 0; o >>= 1) {
        if (t < o) sm[t] += sm[t + o];
        __syncthreads();
    }
    if (t == 0) d_bsum[b] = sm[0];
}

__global__ __launch_bounds__(512) void scanB_kernel() {
    __shared__ int sm[512];
    int t = threadIdx.x;
    sm[t] = (t < NBLK) ? d_bsum[t] : 0;
    __syncthreads();
    for (int o = 1; o < 512; o <<= 1) {
        int v = 0;
        if (t >= o) v = sm[t - o];
        __syncthreads();
        sm[t] += v;
        __syncthreads();
    }
    if (t < NBLK) d_bsum[t] = (t == 0) ? 0 : sm[t - 1];
}

__global__ __launch_bounds__(256) void scanC_kernel() {
    __shared__ int sm[256];
    int b = blockIdx.x, t = threadIdx.x, i = b * 256 + t;
    int c = (i < NN) ? d_cnt_in[i] : 0;
    sm[t] = c;
    __syncthreads();
    for (int o = 1; o < 256; o <<= 1) {
        int v = 0;
        if (t >= o) v = sm[t - o];
        __syncthreads();
        sm[t] += v;
        __syncthreads();
    }
    if (i < NN) d_rowstart[i] = sm[t] - c + d_bsum[b];
    if (i == 0) d_rowstart[NN] = EE;
}

__global__ __launch_bounds__(256)
void fill_kernel(const int* __restrict__ src, const int* __restrict__ dst,
                 const float* __restrict__ ew) {
    int e = blockIdx.x * blockDim.x + threadIdx.x;
    if (e < EE) {
        int d = dst[e];
        int p = d_rowstart[d] + atomicAdd(&d_cursor[d], 1);
        d_srcs[p] = src[e];
        d_ws[p]   = ew[e];
    }
}

// ---------------- tiled GEMM, f32x2, CTA=128x128, thread=8x8 ----------------
// POOL=false: Y[r] = (RS? scale[r]:1) * X[r] @ W        (grid = ceil(NN/128))
// POOL=true : pool[g] += sum_r leaky(X[r]@W + bias)     (grid = GG*8, graph-aligned)
template <int K, bool RS, bool POOL>
__global__ __launch_bounds__(256)
void gemm_kernel(const float* __restrict__ X,
                 const float* __restrict__ W,          // K x 128 row-major
                 const float* __restrict__ rowscale,
                 const float* __restrict__ bias,
                 float* __restrict__ Y,
                 float* __restrict__ pool) {
    __shared__ float Xs[32][128];
    __shared__ float Ws[32][128];
    __shared__ float psum[128];
    __shared__ float bsm[128];
    int tid = threadIdx.x;
    int tx = tid & 15;   // col group: cols tx*8 .. tx*8+7
    int ty = tid >> 4;   // row group: rows ty*8 .. ty*8+7

    int row0, g = 0, validrows = 128;
    if (POOL) {
        g = blockIdx.x >> 3;
        int chunk = blockIdx.x & 7;
        row0 = g * NPG + chunk * 128;
        validrows = NPG - chunk * 128; if (validrows > 128) validrows = 128;
        if (tid < 128) { psum[tid] = 0.f; bsm[tid] = bias[tid]; }
    } else {
        row0 = blockIdx.x * 128;
    }

    u64 acc[32];
#pragma unroll
    for (int i = 0; i < 32; i++) acc[i] = 0ull;

    for (int k0 = 0; k0 < K; k0 += 32) {
        __syncthreads();
        // X chunk -> Xs[k][row] (transposed), rowscale applied, OOB zero
        // 1024 float4 slots: row = s>>3 (0..127), kq = s&7 (8 float4s of 32 k)
#pragma unroll
        for (int i = 0; i < 4; i++) {
            int s = tid + i * 256;
            int row = s >> 3;
            int kq = s & 7;
            int grow = row0 + row;
            float4 v = make_float4(0.f, 0.f, 0.f, 0.f);
            if (grow < NN) {
                v = *(const float4*)(X + (size_t)grow * K + k0 + kq * 4);
                if (RS) {
                    float sc = rowscale[grow];
                    v.x *= sc; v.y *= sc; v.z *= sc; v.w *= sc;
                }
            }
            Xs[kq * 4 + 0][row] = v.x;
            Xs[kq * 4 + 1][row] = v.y;
            Xs[kq * 4 + 2][row] = v.z;
            Xs[kq * 4 + 3][row] = v.w;
        }
        // W chunk -> Ws[k][col]
        // 1024 float4 slots: k = s>>5 (0..31), cq = s&31 (32 float4s per k-row)
#pragma unroll
        for (int i = 0; i < 4; i++) {
            int s = tid + i * 256;
            int k = s >> 5;
            int cq = s & 31;
            *(float4*)&Ws[k][cq * 4] =
                *(const float4*)(W + (size_t)(k0 + k) * 128 + cq * 4);
        }
        __syncthreads();

#pragma unroll 8
        for (int kk = 0; kk < 32; kk++) {
            float xr[8];
            *(float4*)&xr[0] = *(const float4*)&Xs[kk][ty * 8];
            *(float4*)&xr[4] = *(const float4*)&Xs[kk][ty * 8 + 4];
            u64 x2[8];
#pragma unroll
            for (int r = 0; r < 8; r++) x2[r] = pack2(xr[r], xr[r]);
            const double2* wp = (const double2*)&Ws[kk][tx * 8];
            double2 wa = wp[0], wb = wp[1];
            u64 w2[4];
            w2[0] = __double_as_longlong(wa.x);
            w2[1] = __double_as_longlong(wa.y);
            w2[2] = __double_as_longlong(wb.x);
            w2[3] = __double_as_longlong(wb.y);
#pragma unroll
            for (int r = 0; r < 8; r++) {
#pragma unroll
                for (int c = 0; c < 4; c++)
                    acc[r * 4 + c] = ffma2(x2[r], w2[c], acc[r * 4 + c]);
            }
        }
    }

    if (!POOL) {
#pragma unroll
        for (int rr = 0; rr < 8; rr++) {
            int grow = row0 + ty * 8 + rr;
            if (grow < NN) {
                float2 p0 = unpack2(acc[rr * 4 + 0]);
                float2 p1 = unpack2(acc[rr * 4 + 1]);
                float2 p2 = unpack2(acc[rr * 4 + 2]);
                float2 p3 = unpack2(acc[rr * 4 + 3]);
                float* yp = Y + (size_t)grow * 128 + tx * 8;
                *(float4*)yp       = make_float4(p0.x, p0.y, p1.x, p1.y);
                *(float4*)(yp + 4) = make_float4(p2.x, p2.y, p3.x, p3.y);
            }
        }
    } else {
        float b[8];
#pragma unroll
        for (int j = 0; j < 8; j++) b[j] = bsm[tx * 8 + j];
        float cs[8];
#pragma unroll
        for (int j = 0; j < 8; j++) cs[j] = 0.f;
#pragma unroll
        for (int rr = 0; rr < 8; rr++) {
            if (ty * 8 + rr < validrows) {
#pragma unroll
                for (int c = 0; c < 4; c++) {
                    float2 p = unpack2(acc[rr * 4 + c]);
                    cs[2 * c]     += leaky(p.x + b[2 * c]);
                    cs[2 * c + 1] += leaky(p.y + b[2 * c + 1]);
                }
            }
        }
#pragma unroll
        for (int j = 0; j < 8; j++) atomicAdd(&psum[tx * 8 + j], cs[j]);
        __syncthreads();
        if (tid < 128) atomicAdd(&pool[g * 128 + tid], psum[tid]);
    }
}

// ---------------- edge aggregation (CSR by dst, warp per node) ----------------
__global__ __launch_bounds__(256)
void conv_kernel(const float* __restrict__ hpre, float* __restrict__ out) {
    int gt = blockIdx.x * blockDim.x + threadIdx.x;
    int node = gt >> 5;
    int lane = gt & 31;
    if (node >= NN) return;
    int e0 = d_rowstart[node];
    int e1 = d_rowstart[node + 1];
    const float4* hp = (const float4*)hpre;
    float4 acc = make_float4(0.f, 0.f, 0.f, 0.f);
    for (int e = e0; e < e1; e++) {
        int s = d_srcs[e];
        float w = d_ws[e];
        float4 v = hp[(size_t)s * 32 + lane];
        acc.x += v.x * w; acc.y += v.y * w;
        acc.z += v.z * w; acc.w += v.w * w;
    }
    float sc = d_inis[node];
    acc.x *= sc; acc.y *= sc; acc.z *= sc; acc.w *= sc;
    ((float4*)out)[(size_t)node * 32 + lane] = acc;
}

// ---------------- GraphNorm stats (4 CTAs per graph) ----------------
__global__ __launch_bounds__(256)
void normA_kernel(const float* __restrict__ Yin,
                  float* __restrict__ S1, float* __restrict__ S2) {
    int g = blockIdx.x >> 2;
    int q = blockIdx.x & 3;
    int f = threadIdx.x & 127;
    int half = threadIdx.x >> 7;
    const float* base = Yin + ((size_t)g * NPG + q * 250 + half * 125) * HH + f;
    float s1 = 0.f, s2 = 0.f;
#pragma unroll 5
    for (int i = 0; i < 125; i++) {
        float v = base[(size_t)i * HH];
        s1 += v;
        s2 += v * v;
    }
    __shared__ float sm1[256], sm2[256];
    sm1[threadIdx.x] = s1;
    sm2[threadIdx.x] = s2;
    __syncthreads();
    if (half == 0) {
        atomicAdd(&S1[g * HH + f], sm1[f] + sm1[128 + f]);
        atomicAdd(&S2[g * HH + f], sm2[f] + sm2[128 + f]);
    }
}

// ---------------- GraphNorm apply + leaky + fused m-pool (raw sums) ----------------
__global__ __launch_bounds__(256)
void normB_kernel(const float* __restrict__ Yin,
                  const float* __restrict__ S1, const float* __restrict__ S2,
                  const float* __restrict__ alpha, const float* __restrict__ gamma_,
                  const float* __restrict__ beta, float* __restrict__ Yout,
                  float* __restrict__ mout) {
    int g = blockIdx.x >> 2;
    int q = blockIdx.x & 3;
    int f = threadIdx.x & 127;
    int half = threadIdx.x >> 7;
    float a = alpha[f], gm = gamma_[f], bt = beta[f];
    float mean = S1[g * HH + f] * (1.f / NPG);
    float var = S2[g * HH + f] * (1.f / NPG) - (2.f * a - a * a) * mean * mean;
    float inv = rsqrtf(var + EPSN);
    float am = a * mean;
    size_t off = ((size_t)g * NPG + q * 250 + half * 125) * HH + f;
    const float* base = Yin + off;
    float* obase = Yout + off;
    float so = 0.f;
#pragma unroll 5
    for (int i = 0; i < 125; i++) {
        float v = base[(size_t)i * HH];
        float o = leaky(gm * (v - am) * inv + bt);
        obase[(size_t)i * HH] = o;
        so += o;
    }
    __shared__ float sm[256];
    sm[threadIdx.x] = so;
    __syncthreads();
    if (half == 0) atomicAdd(&mout[g * HH + f], sm[f] + sm[128 + f]);
}

// ---------------- final readout assembly ----------------
__global__ __launch_bounds__(128)
void final_kernel(const float* __restrict__ p1, const float* __restrict__ m1,
                  const float* __restrict__ p2, const float* __restrict__ m2,
                  const float* __restrict__ r1w2, const float* __restrict__ r1b2,
                  const float* __restrict__ r2w2, const float* __restrict__ r2b2,
                  float* __restrict__ out) {
    int g = blockIdx.x;
    int t = threadIdx.x;
    const float inv = 1.f / NPG;
    if (t < RD) {
        float a1 = 0.f, a2 = 0.f;
        const float* pp1 = p1 + g * HH;
        const float* pp2 = p2 + g * HH;
#pragma unroll 4
        for (int f = 0; f < HH; f++) {
            a1 += pp1[f] * r1w2[f * RD + t];
            a2 += pp2[f] * r2w2[f * RD + t];
        }
        a1 = a1 * inv + r1b2[t];
        a2 = a2 * inv + r2b2[t];
        out[g * 384 + t]       = leaky(leaky(a1));
        out[g * 384 + 192 + t] = leaky(leaky(a2));
    }
    out[g * 384 + 64 + t]  = leaky(m1[g * HH + t] * inv);
    out[g * 384 + 256 + t] = leaky(m2[g * HH + t] * inv);
}

// ---------------- host launch ----------------
extern "C" void kernel_launch(void* const* d_in, const int* in_sizes, int n_in,
                              void* d_out, int out_size) {
    const float* node_feats = (const float*)d_in[0];
    const float* ew         = (const float*)d_in[1];
    const float* W1         = (const float*)d_in[2];
    const float* W2         = (const float*)d_in[3];
    const float* gn1a       = (const float*)d_in[4];
    const float* gn1g       = (const float*)d_in[5];
    const float* gn1b       = (const float*)d_in[6];
    const float* gn2a       = (const float*)d_in[7];
    const float* gn2g       = (const float*)d_in[8];
    const float* gn2b       = (const float*)d_in[9];
    const float* r1w1       = (const float*)d_in[10];
    const float* r1b1       = (const float*)d_in[11];
    const float* r1w2       = (const float*)d_in[12];
    const float* r1b2       = (const float*)d_in[13];
    const float* r2w1       = (const float*)d_in[14];
    const float* r2b1       = (const float*)d_in[15];
    const float* r2w2       = (const float*)d_in[16];
    const float* r2b2       = (const float*)d_in[17];
    const int*   src        = (const int*)d_in[18];
    const int*   dst        = (const int*)d_in[19];
    float* out = (float*)d_out;

    void *hpre, *conv, *hpost, *pool1, *m1, *pool2, *m2, *outis;
    void *s1a, *s2a, *s1b, *s2b;
    cudaGetSymbolAddress(&hpre,  d_hpre);
    cudaGetSymbolAddress(&conv,  d_conv);
    cudaGetSymbolAddress(&hpost, d_hpost);
    cudaGetSymbolAddress(&pool1, d_pool1);
    cudaGetSymbolAddress(&m1,    d_m1);
    cudaGetSymbolAddress(&pool2, d_pool2);
    cudaGetSymbolAddress(&m2,    d_m2);
    cudaGetSymbolAddress(&outis, d_outis);
    cudaGetSymbolAddress(&s1a,   d_S1a);
    cudaGetSymbolAddress(&s2a,   d_S2a);
    cudaGetSymbolAddress(&s1b,   d_S1b);
    cudaGetSymbolAddress(&s2b,   d_S2b);

    const int EB = (EE + 255) / 256;       // 6250
    const int CB = (NN * 32 + 255) / 256;  // 12500
    const int GB = (NN + 127) / 128;       // 782
    const int PB = GG * 8;                 // 800

    // CSR build + degrees
    zero_kernel<<<NBLK, 256>>>();
    hist_kernel<<<EB, 256>>>(src, dst);
    isqrt_kernel<<<NBLK, 256>>>();
    scanA_kernel<<<NBLK, 256>>>();
    scanB_kernel<<<1, 512>>>();
    scanC_kernel<<<NBLK, 256>>>();
    fill_kernel<<<EB, 256>>>(src, dst, ew);

    // ---- layer 1 ----
    gemm_kernel<64, true, false><<<GB, 256>>>(
        node_feats, W1, (const float*)outis, nullptr, (float*)hpre, nullptr);
    conv_kernel<<<CB, 256>>>((const float*)hpre, (float*)conv);
    normA_kernel<<<GG * 4, 256>>>((const float*)conv, (float*)s1a, (float*)s2a);
    normB_kernel<<<GG * 4, 256>>>((const float*)conv, (const float*)s1a, (const float*)s2a,
                                  gn1a, gn1g, gn1b, (float*)hpost, (float*)m1);

    // readout1 phi (fused pool)
    gemm_kernel<128, false, true><<<PB, 256>>>(
        (const float*)hpost, r1w1, nullptr, r1b1, nullptr, (float*)pool1);

    // ---- layer 2 ----
    gemm_kernel<128, true, false><<<GB, 256>>>(
        (const float*)hpost, W2, (const float*)outis, nullptr, (float*)hpre, nullptr);
    conv_kernel<<<CB, 256>>>((const float*)hpre, (float*)conv);
    normA_kernel<<<GG * 4, 256>>>((const float*)conv, (float*)s1b, (float*)s2b);
    normB_kernel<<<GG * 4, 256>>>((const float*)conv, (const float*)s1b, (const float*)s2b,
                                  gn2a, gn2g, gn2b, (float*)hpost, (float*)m2);

    gemm_kernel<128, false, true><<<PB, 256>>>(
        (const float*)hpost, r2w1, nullptr, r2b1, nullptr, (float*)pool2);

    final_kernel<<<GG, 128>>>((const float*)pool1, (const float*)m1,
                              (const float*)pool2, (const float*)m2,
                              r1w2, r1b2, r2w2, r2b2, out);
}

// round 7
// speedup vs baseline: 2.4728x; 1.0855x over previous
#include <cuda_runtime.h>
#include <cuda_fp16.h>
#include <cstddef>

#define NN   100000
#define EE   1600000
#define GG   100
#define NPG  1000
#define EPG  16000
#define HH   128
#define FIN  64
#define RD   64
#define SLOPE 0.01f
#define EPSN  1e-5f

typedef unsigned long long u64;
typedef unsigned int u32;

__device__ __forceinline__ u64 pack2(float a, float b) {
    u64 r; asm("mov.b64 %0,{%1,%2};" : "=l"(r) : "f"(a), "f"(b)); return r;
}
__device__ __forceinline__ u64 ffma2(u64 a, u64 b, u64 c) {
    u64 d; asm("fma.rn.f32x2 %0,%1,%2,%3;" : "=l"(d) : "l"(a), "l"(b), "l"(c)); return d;
}
__device__ __forceinline__ float2 unpack2(u64 v) {
    float2 f; asm("mov.b64 {%0,%1},%2;" : "=f"(f.x), "=f"(f.y) : "l"(v)); return f;
}
__device__ __forceinline__ float leaky(float x) { return x >= 0.f ? x : SLOPE * x; }

// ---------------- scratch ----------------
__device__ int    d_rowstart[NN + 1];
__device__ int    d_srcs[EE];
__device__ float  d_ws[EE];
__device__ float  d_outis[NN];
__device__ float  d_inis[NN];
__device__ __half d_hpre16[(size_t)NN * HH];
__device__ float  d_conv[(size_t)NN * HH];
__device__ float  d_hpost[(size_t)NN * HH];
__device__ float  d_pool1[GG * HH];
__device__ float  d_m1[GG * HH];
__device__ float  d_pool2[GG * HH];
__device__ float  d_m2[GG * HH];
__device__ float  d_S1a[GG * HH];
__device__ float  d_S2a[GG * HH];
__device__ float  d_S1b[GG * HH];
__device__ float  d_S2b[GG * HH];

// ---------------- zero small accumulators ----------------
__global__ __launch_bounds__(256) void zero_kernel() {
    int i = blockIdx.x * blockDim.x + threadIdx.x;
    if (i < GG * HH) {
        d_pool1[i] = 0.f; d_pool2[i] = 0.f;
        d_m1[i] = 0.f;    d_m2[i] = 0.f;
        d_S1a[i] = 0.f;   d_S2a[i] = 0.f;
        d_S1b[i] = 0.f;   d_S2b[i] = 0.f;
    }
}

// ---------------- fused per-graph CSR build (1 CTA per graph, smem only) ----------------
__global__ __launch_bounds__(256)
void csr_kernel(const int* __restrict__ src, const int* __restrict__ dst,
                const float* __restrict__ ew) {
    __shared__ int cin[NPG], cout[NPG], cur[NPG], part[256];
    int g = blockIdx.x, t = threadIdx.x;
    int nbase = g * NPG;
    int e0 = g * EPG;

    for (int i = t; i < NPG; i += 256) { cin[i] = 0; cout[i] = 0; }
    __syncthreads();

    // histogram (smem atomics)
    for (int e = t; e < EPG; e += 256) {
        atomicAdd(&cin[dst[e0 + e] - nbase], 1);
        atomicAdd(&cout[src[e0 + e] - nbase], 1);
    }
    __syncthreads();

    // degrees -> inverse sqrt
    for (int i = t; i < NPG; i += 256) {
        int ci = cin[i];  if (ci < 1) ci = 1;
        int co = cout[i]; if (co < 1) co = 1;
        d_inis[nbase + i]  = rsqrtf((float)ci);
        d_outis[nbase + i] = rsqrtf((float)co);
    }

    // exclusive scan of cin (250 threads x 4 items)
    int s = 0;
    if (t < 250) {
#pragma unroll
        for (int j = 0; j < 4; j++) s += cin[t * 4 + j];
    }
    part[t] = s;
    __syncthreads();
    for (int o = 1; o < 256; o <<= 1) {
        int v = 0;
        if (t >= o) v = part[t - o];
        __syncthreads();
        part[t] += v;
        __syncthreads();
    }
    int run = (t == 0) ? 0 : part[t - 1];
    if (t < 250) {
#pragma unroll
        for (int j = 0; j < 4; j++) {
            int i = t * 4 + j;
            int c = cin[i];
            cur[i] = run;
            d_rowstart[nbase + i] = e0 + run;
            run += c;
        }
    }
    if (g == 0 && t == 255) d_rowstart[NN] = EE;
    __syncthreads();

    // fill (smem cursors)
    for (int e = t; e < EPG; e += 256) {
        int d = dst[e0 + e] - nbase;
        int p = atomicAdd(&cur[d], 1);
        d_srcs[e0 + p] = src[e0 + e];
        d_ws[e0 + p]   = ew[e0 + e];
    }
}

// ---------------- tiled GEMM, f32x2, CTA=128x128, thread=8x8 ----------------
// POOL=false: Y[r] = (RS? scale[r]:1) * X[r] @ W   (OUT16: Y is __half)
// POOL=true : pool[g] += sum_r leaky(X[r]@W + bias)
template <int K, bool RS, bool POOL, bool OUT16>
__global__ __launch_bounds__(256)
void gemm_kernel(const float* __restrict__ X,
                 const float* __restrict__ W,          // K x 128 row-major
                 const float* __restrict__ rowscale,
                 const float* __restrict__ bias,
                 void* __restrict__ Yv,
                 float* __restrict__ pool) {
    __shared__ float Xs[32][128];
    __shared__ float Ws[32][128];
    __shared__ float psum[128];
    __shared__ float bsm[128];
    int tid = threadIdx.x;
    int tx = tid & 15;
    int ty = tid >> 4;

    int row0, g = 0, validrows = 128;
    if (POOL) {
        g = blockIdx.x >> 3;
        int chunk = blockIdx.x & 7;
        row0 = g * NPG + chunk * 128;
        validrows = NPG - chunk * 128; if (validrows > 128) validrows = 128;
        if (tid < 128) { psum[tid] = 0.f; bsm[tid] = bias[tid]; }
    } else {
        row0 = blockIdx.x * 128;
    }

    u64 acc[32];
#pragma unroll
    for (int i = 0; i < 32; i++) acc[i] = 0ull;

    for (int k0 = 0; k0 < K; k0 += 32) {
        __syncthreads();
#pragma unroll
        for (int i = 0; i < 4; i++) {
            int s = tid + i * 256;
            int row = s >> 3;
            int kq = s & 7;
            int grow = row0 + row;
            float4 v = make_float4(0.f, 0.f, 0.f, 0.f);
            if (grow < NN) {
                v = *(const float4*)(X + (size_t)grow * K + k0 + kq * 4);
                if (RS) {
                    float sc = rowscale[grow];
                    v.x *= sc; v.y *= sc; v.z *= sc; v.w *= sc;
                }
            }
            Xs[kq * 4 + 0][row] = v.x;
            Xs[kq * 4 + 1][row] = v.y;
            Xs[kq * 4 + 2][row] = v.z;
            Xs[kq * 4 + 3][row] = v.w;
        }
#pragma unroll
        for (int i = 0; i < 4; i++) {
            int s = tid + i * 256;
            int k = s >> 5;
            int cq = s & 31;
            *(float4*)&Ws[k][cq * 4] =
                *(const float4*)(W + (size_t)(k0 + k) * 128 + cq * 4);
        }
        __syncthreads();

#pragma unroll 8
        for (int kk = 0; kk < 32; kk++) {
            float xr[8];
            *(float4*)&xr[0] = *(const float4*)&Xs[kk][ty * 8];
            *(float4*)&xr[4] = *(const float4*)&Xs[kk][ty * 8 + 4];
            u64 x2[8];
#pragma unroll
            for (int r = 0; r < 8; r++) x2[r] = pack2(xr[r], xr[r]);
            const double2* wp = (const double2*)&Ws[kk][tx * 8];
            double2 wa = wp[0], wb = wp[1];
            u64 w2[4];
            w2[0] = __double_as_longlong(wa.x);
            w2[1] = __double_as_longlong(wa.y);
            w2[2] = __double_as_longlong(wb.x);
            w2[3] = __double_as_longlong(wb.y);
#pragma unroll
            for (int r = 0; r < 8; r++) {
#pragma unroll
                for (int c = 0; c < 4; c++)
                    acc[r * 4 + c] = ffma2(x2[r], w2[c], acc[r * 4 + c]);
            }
        }
    }

    if (!POOL) {
#pragma unroll
        for (int rr = 0; rr < 8; rr++) {
            int grow = row0 + ty * 8 + rr;
            if (grow < NN) {
                float2 p0 = unpack2(acc[rr * 4 + 0]);
                float2 p1 = unpack2(acc[rr * 4 + 1]);
                float2 p2 = unpack2(acc[rr * 4 + 2]);
                float2 p3 = unpack2(acc[rr * 4 + 3]);
                if (OUT16) {
                    __half2 h0 = __floats2half2_rn(p0.x, p0.y);
                    __half2 h1 = __floats2half2_rn(p1.x, p1.y);
                    __half2 h2 = __floats2half2_rn(p2.x, p2.y);
                    __half2 h3 = __floats2half2_rn(p3.x, p3.y);
                    uint4 u;
                    u.x = *(u32*)&h0; u.y = *(u32*)&h1;
                    u.z = *(u32*)&h2; u.w = *(u32*)&h3;
                    *(uint4*)((__half*)Yv + (size_t)grow * 128 + tx * 8) = u;
                } else {
                    float* yp = (float*)Yv + (size_t)grow * 128 + tx * 8;
                    *(float4*)yp       = make_float4(p0.x, p0.y, p1.x, p1.y);
                    *(float4*)(yp + 4) = make_float4(p2.x, p2.y, p3.x, p3.y);
                }
            }
        }
    } else {
        float b[8];
#pragma unroll
        for (int j = 0; j < 8; j++) b[j] = bsm[tx * 8 + j];
        float cs[8];
#pragma unroll
        for (int j = 0; j < 8; j++) cs[j] = 0.f;
#pragma unroll
        for (int rr = 0; rr < 8; rr++) {
            if (ty * 8 + rr < validrows) {
#pragma unroll
                for (int c = 0; c < 4; c++) {
                    float2 p = unpack2(acc[rr * 4 + c]);
                    cs[2 * c]     += leaky(p.x + b[2 * c]);
                    cs[2 * c + 1] += leaky(p.y + b[2 * c + 1]);
                }
            }
        }
#pragma unroll
        for (int j = 0; j < 8; j++) atomicAdd(&psum[tx * 8 + j], cs[j]);
        __syncthreads();
        if (tid < 128) atomicAdd(&pool[g * 128 + tid], psum[tid]);
    }
}

// ---------------- edge aggregation (CSR by dst, warp per node, fp16 gather) ----------------
__global__ __launch_bounds__(256)
void conv_kernel(const __half* __restrict__ hpre, float* __restrict__ out) {
    int gt = blockIdx.x * blockDim.x + threadIdx.x;
    int node = gt >> 5;
    int lane = gt & 31;
    if (node >= NN) return;
    int e0 = d_rowstart[node];
    int e1 = d_rowstart[node + 1];
    const uint2* hp = (const uint2*)hpre;   // 4 halves per lane
    float4 acc = make_float4(0.f, 0.f, 0.f, 0.f);
    for (int e = e0; e < e1; e++) {
        int s = d_srcs[e];
        float w = d_ws[e];
        uint2 v = hp[(size_t)s * 32 + lane];
        float2 fa = __half22float2(*(__half2*)&v.x);
        float2 fb = __half22float2(*(__half2*)&v.y);
        acc.x += fa.x * w; acc.y += fa.y * w;
        acc.z += fb.x * w; acc.w += fb.y * w;
    }
    float sc = d_inis[node];
    acc.x *= sc; acc.y *= sc; acc.z *= sc; acc.w *= sc;
    ((float4*)out)[(size_t)node * 32 + lane] = acc;
}

// ---------------- GraphNorm stats (4 CTAs per graph) ----------------
__global__ __launch_bounds__(256)
void normA_kernel(const float* __restrict__ Yin,
                  float* __restrict__ S1, float* __restrict__ S2) {
    int g = blockIdx.x >> 2;
    int q = blockIdx.x & 3;
    int f = threadIdx.x & 127;
    int half = threadIdx.x >> 7;
    const float* base = Yin + ((size_t)g * NPG + q * 250 + half * 125) * HH + f;
    float s1 = 0.f, s2 = 0.f;
#pragma unroll 5
    for (int i = 0; i < 125; i++) {
        float v = base[(size_t)i * HH];
        s1 += v;
        s2 += v * v;
    }
    __shared__ float sm1[256], sm2[256];
    sm1[threadIdx.x] = s1;
    sm2[threadIdx.x] = s2;
    __syncthreads();
    if (half == 0) {
        atomicAdd(&S1[g * HH + f], sm1[f] + sm1[128 + f]);
        atomicAdd(&S2[g * HH + f], sm2[f] + sm2[128 + f]);
    }
}

// ---------------- GraphNorm apply + leaky + fused m-pool (raw sums) ----------------
__global__ __launch_bounds__(256)
void normB_kernel(const float* __restrict__ Yin,
                  const float* __restrict__ S1, const float* __restrict__ S2,
                  const float* __restrict__ alpha, const float* __restrict__ gamma_,
                  const float* __restrict__ beta, float* __restrict__ Yout,
                  float* __restrict__ mout) {
    int g = blockIdx.x >> 2;
    int q = blockIdx.x & 3;
    int f = threadIdx.x & 127;
    int half = threadIdx.x >> 7;
    float a = alpha[f], gm = gamma_[f], bt = beta[f];
    float mean = S1[g * HH + f] * (1.f / NPG);
    float var = S2[g * HH + f] * (1.f / NPG) - (2.f * a - a * a) * mean * mean;
    float inv = rsqrtf(var + EPSN);
    float am = a * mean;
    size_t off = ((size_t)g * NPG + q * 250 + half * 125) * HH + f;
    const float* base = Yin + off;
    float* obase = Yout + off;
    float so = 0.f;
#pragma unroll 5
    for (int i = 0; i < 125; i++) {
        float v = base[(size_t)i * HH];
        float o = leaky(gm * (v - am) * inv + bt);
        obase[(size_t)i * HH] = o;
        so += o;
    }
    __shared__ float sm[256];
    sm[threadIdx.x] = so;
    __syncthreads();
    if (half == 0) atomicAdd(&mout[g * HH + f], sm[f] + sm[128 + f]);
}

// ---------------- final readout assembly ----------------
__global__ __launch_bounds__(128)
void final_kernel(const float* __restrict__ p1, const float* __restrict__ m1,
                  const float* __restrict__ p2, const float* __restrict__ m2,
                  const float* __restrict__ r1w2, const float* __restrict__ r1b2,
                  const float* __restrict__ r2w2, const float* __restrict__ r2b2,
                  float* __restrict__ out) {
    int g = blockIdx.x;
    int t = threadIdx.x;
    const float inv = 1.f / NPG;
    if (t < RD) {
        float a1 = 0.f, a2 = 0.f;
        const float* pp1 = p1 + g * HH;
        const float* pp2 = p2 + g * HH;
#pragma unroll 4
        for (int f = 0; f < HH; f++) {
            a1 += pp1[f] * r1w2[f * RD + t];
            a2 += pp2[f] * r2w2[f * RD + t];
        }
        a1 = a1 * inv + r1b2[t];
        a2 = a2 * inv + r2b2[t];
        out[g * 384 + t]       = leaky(leaky(a1));
        out[g * 384 + 192 + t] = leaky(leaky(a2));
    }
    out[g * 384 + 64 + t]  = leaky(m1[g * HH + t] * inv);
    out[g * 384 + 256 + t] = leaky(m2[g * HH + t] * inv);
}

// ---------------- host launch ----------------
extern "C" void kernel_launch(void* const* d_in, const int* in_sizes, int n_in,
                              void* d_out, int out_size) {
    const float* node_feats = (const float*)d_in[0];
    const float* ew         = (const float*)d_in[1];
    const float* W1         = (const float*)d_in[2];
    const float* W2         = (const float*)d_in[3];
    const float* gn1a       = (const float*)d_in[4];
    const float* gn1g       = (const float*)d_in[5];
    const float* gn1b       = (const float*)d_in[6];
    const float* gn2a       = (const float*)d_in[7];
    const float* gn2g       = (const float*)d_in[8];
    const float* gn2b       = (const float*)d_in[9];
    const float* r1w1       = (const float*)d_in[10];
    const float* r1b1       = (const float*)d_in[11];
    const float* r1w2       = (const float*)d_in[12];
    const float* r1b2       = (const float*)d_in[13];
    const float* r2w1       = (const float*)d_in[14];
    const float* r2b1       = (const float*)d_in[15];
    const float* r2w2       = (const float*)d_in[16];
    const float* r2b2       = (const float*)d_in[17];
    const int*   src        = (const int*)d_in[18];
    const int*   dst        = (const int*)d_in[19];
    float* out = (float*)d_out;

    void *hpre16, *conv, *hpost, *pool1, *m1, *pool2, *m2, *outis;
    void *s1a, *s2a, *s1b, *s2b;
    cudaGetSymbolAddress(&hpre16, d_hpre16);
    cudaGetSymbolAddress(&conv,   d_conv);
    cudaGetSymbolAddress(&hpost,  d_hpost);
    cudaGetSymbolAddress(&pool1,  d_pool1);
    cudaGetSymbolAddress(&m1,     d_m1);
    cudaGetSymbolAddress(&pool2,  d_pool2);
    cudaGetSymbolAddress(&m2,     d_m2);
    cudaGetSymbolAddress(&outis,  d_outis);
    cudaGetSymbolAddress(&s1a,    d_S1a);
    cudaGetSymbolAddress(&s2a,    d_S2a);
    cudaGetSymbolAddress(&s1b,    d_S1b);
    cudaGetSymbolAddress(&s2b,    d_S2b);

    const int CB = (NN * 32 + 255) / 256;  // 12500
    const int GB = (NN + 127) / 128;       // 782
    const int PB = GG * 8;                 // 800

    zero_kernel<<<50, 256>>>();
    csr_kernel<<<GG, 256>>>(src, dst, ew);

    // ---- layer 1 ----
    gemm_kernel<64, true, false, true><<<GB, 256>>>(
        node_feats, W1, (const float*)outis, nullptr, hpre16, nullptr);
    conv_kernel<<<CB, 256>>>((const __half*)hpre16, (float*)conv);
    normA_kernel<<<GG * 4, 256>>>((const float*)conv, (float*)s1a, (float*)s2a);
    normB_kernel<<<GG * 4, 256>>>((const float*)conv, (const float*)s1a, (const float*)s2a,
                                  gn1a, gn1g, gn1b, (float*)hpost, (float*)m1);

    gemm_kernel<128, false, true, false><<<PB, 256>>>(
        (const float*)hpost, r1w1, nullptr, r1b1, nullptr, (float*)pool1);

    // ---- layer 2 ----
    gemm_kernel<128, true, false, true><<<GB, 256>>>(
        (const float*)hpost, W2, (const float*)outis, nullptr, hpre16, nullptr);
    conv_kernel<<<CB, 256>>>((const __half*)hpre16, (float*)conv);
    normA_kernel<<<GG * 4, 256>>>((const float*)conv, (float*)s1b, (float*)s2b);
    normB_kernel<<<GG * 4, 256>>>((const float*)conv, (const float*)s1b, (const float*)s2b,
                                  gn2a, gn2g, gn2b, (float*)hpost, (float*)m2);

    gemm_kernel<128, false, true, false><<<PB, 256>>>(
        (const float*)hpost, r2w1, nullptr, r2b1, nullptr, (float*)pool2);

    final_kernel<<<GG, 128>>>((const float*)pool1, (const float*)m1,
                              (const float*)pool2, (const float*)m2,
                              r1w2, r1b2, r2w2, r2b2, out);
}